// round 2
// baseline (speedup 1.0000x reference)
#include <cuda_runtime.h>
#include <cstdint>

#define N_PTS 400000
#define DIM   128
#define KNB   27
#define NSEG  8
#define TILE  64
#define NTHR  256

// ---------------- scratch (static device globals: allocation-free) ----------------
__device__ float g_out1[(size_t)N_PTS * DIM];
__device__ float g_out2[(size_t)N_PTS * DIM];
__device__ float g_segsum[NSEG * DIM];
__device__ float g_segmean[NSEG * DIM];
__device__ int   g_segcnt[NSEG];

// ---------------- packed f32x2 helpers (ptxas won't fuse FFMA2 from C++) ----------
__device__ __forceinline__ void fma2(unsigned long long& d, unsigned long long a,
                                     unsigned long long b) {
    asm("fma.rn.f32x2 %0, %1, %2, %0;" : "+l"(d) : "l"(a), "l"(b));
}
__device__ __forceinline__ unsigned long long dup2(float x) {
    unsigned long long r;
    asm("mov.b64 %0, {%1, %1};" : "=l"(r) : "f"(x));
    return r;
}
__device__ __forceinline__ float2 upk(unsigned long long v) {
    float2 r;
    asm("mov.b64 {%0, %1}, %2;" : "=f"(r.x), "=f"(r.y) : "l"(v));
    return r;
}

// ---------------- zero segment accumulators (every launch: graph replays) ---------
__global__ void zero_seg_kernel() {
    int t = blockIdx.x * blockDim.x + threadIdx.x;
    if (t < NSEG * DIM) g_segsum[t] = 0.f;
    if (t < NSEG) g_segcnt[t] = 0;
}

// ---------------- sparse conv: out_m = relu(sum_k mask * feats[idx] @ W_m[k] + b_m)
// grid: (N/TILE, 2).  blockIdx.y selects (W1,b1,out1) vs (W2,b2,out2).
// smem: Ws[128][128] | Gt[128][64] | idx_s[64*27] | msk_s[64*27]
__global__ void __launch_bounds__(NTHR, 2)
conv_kernel(const float* __restrict__ feats,
            const int* __restrict__ nidx,
            const int* __restrict__ nmask,   // harness materializes bool as int32
            const float* __restrict__ W1, const float* __restrict__ b1,
            const float* __restrict__ W2, const float* __restrict__ b2) {
    extern __shared__ char smem_raw[];
    float* Ws = reinterpret_cast<float*>(smem_raw);          // 128*128
    float* Gt = Ws + DIM * DIM;                              // 128*64 (transposed tile)
    int*   idx_s = reinterpret_cast<int*>(Gt + DIM * TILE);  // 64*27
    unsigned char* msk_s = reinterpret_cast<unsigned char*>(idx_s + TILE * KNB);

    const float* W    = blockIdx.y ? W2 : W1;
    const float* bias = blockIdx.y ? b2 : b1;
    float* outp       = blockIdx.y ? g_out2 : g_out1;

    const int t     = threadIdx.x;
    const int nbase = blockIdx.x * TILE;

    // stage neighbor idx + mask for the tile (coalesced)
    for (int i = t; i < TILE * KNB; i += NTHR) {
        idx_s[i] = nidx[(size_t)nbase * KNB + i];
        msk_s[i] = (unsigned char)(nmask[(size_t)nbase * KNB + i] != 0);
    }

    const int cx = t & 15;   // col group: cols [8*cx, 8*cx+8)
    const int py = t >> 4;   // point group: pts [4*py, 4*py+4)
    const int gpt  = t & 63; // gather: point
    const int gseg = t >> 6; // gather: d-range [32*gseg, 32*gseg+32)

    unsigned long long acc[4][4];
#pragma unroll
    for (int i = 0; i < 4; i++)
#pragma unroll
        for (int j = 0; j < 4; j++) acc[i][j] = 0ULL;

    for (int k = 0; k < KNB; k++) {
        __syncthreads();  // protect Ws/Gt reuse
        // stage W[k] (row-major [d][c], matches x@W contraction)
        {
            const float4* Wg = reinterpret_cast<const float4*>(W + (size_t)k * DIM * DIM);
            float4* Ws4 = reinterpret_cast<float4*>(Ws);
#pragma unroll
            for (int i = 0; i < 16; i++) Ws4[t + i * NTHR] = Wg[t + i * NTHR];
        }
        // masked gather -> transposed Gt[d][pt]
        {
            const int id = idx_s[gpt * KNB + k];
            const bool m = msk_s[gpt * KNB + k] != 0;
            const float4* src =
                reinterpret_cast<const float4*>(feats + (size_t)id * DIM) + gseg * 8;
#pragma unroll
            for (int q = 0; q < 8; q++) {
                float4 v = m ? src[q] : make_float4(0.f, 0.f, 0.f, 0.f);
                const int d0 = gseg * 32 + q * 4;
                Gt[(d0 + 0) * TILE + gpt] = v.x;
                Gt[(d0 + 1) * TILE + gpt] = v.y;
                Gt[(d0 + 2) * TILE + gpt] = v.z;
                Gt[(d0 + 3) * TILE + gpt] = v.w;
            }
        }
        __syncthreads();
        // 64x128 += Gt^T(64x128) @ Ws(128x128), f32x2 packed FMAs
#pragma unroll 4
        for (int d = 0; d < DIM; d++) {
            const float4 g = *reinterpret_cast<const float4*>(&Gt[d * TILE + 4 * py]);
            const ulonglong2 w0 =
                *reinterpret_cast<const ulonglong2*>(&Ws[d * DIM + 8 * cx]);
            const ulonglong2 w1 =
                *reinterpret_cast<const ulonglong2*>(&Ws[d * DIM + 8 * cx + 4]);
            const unsigned long long ga = dup2(g.x), gb = dup2(g.y),
                                     gc = dup2(g.z), gd = dup2(g.w);
            fma2(acc[0][0], ga, w0.x); fma2(acc[0][1], ga, w0.y);
            fma2(acc[0][2], ga, w1.x); fma2(acc[0][3], ga, w1.y);
            fma2(acc[1][0], gb, w0.x); fma2(acc[1][1], gb, w0.y);
            fma2(acc[1][2], gb, w1.x); fma2(acc[1][3], gb, w1.y);
            fma2(acc[2][0], gc, w0.x); fma2(acc[2][1], gc, w0.y);
            fma2(acc[2][2], gc, w1.x); fma2(acc[2][3], gc, w1.y);
            fma2(acc[3][0], gd, w0.x); fma2(acc[3][1], gd, w0.y);
            fma2(acc[3][2], gd, w1.x); fma2(acc[3][3], gd, w1.y);
        }
    }

    // epilogue: +bias, relu, store
    const float4 bA = *reinterpret_cast<const float4*>(&bias[8 * cx]);
    const float4 bB = *reinterpret_cast<const float4*>(&bias[8 * cx + 4]);
#pragma unroll
    for (int i = 0; i < 4; i++) {
        const int row = nbase + 4 * py + i;
        const float2 a0 = upk(acc[i][0]), a1 = upk(acc[i][1]);
        const float2 a2 = upk(acc[i][2]), a3 = upk(acc[i][3]);
        float4 r0, r1;
        r0.x = fmaxf(a0.x + bA.x, 0.f); r0.y = fmaxf(a0.y + bA.y, 0.f);
        r0.z = fmaxf(a1.x + bA.z, 0.f); r0.w = fmaxf(a1.y + bA.w, 0.f);
        r1.x = fmaxf(a2.x + bB.x, 0.f); r1.y = fmaxf(a2.y + bB.y, 0.f);
        r1.z = fmaxf(a3.x + bB.z, 0.f); r1.w = fmaxf(a3.y + bB.w, 0.f);
        float* op = outp + (size_t)row * DIM + 8 * cx;
        *reinterpret_cast<float4*>(op)     = r0;
        *reinterpret_cast<float4*>(op + 4) = r1;
    }
}

// ---------------- segment sums of out2 (+counts); segment_ids are sorted ----------
__global__ void segreduce_kernel(const int* __restrict__ segid) {
    const int RPB = 512, HALF = 256;
    const int c = threadIdx.x & 127;
    const int h = threadIdx.x >> 7;
    const int r0 = blockIdx.x * RPB + h * HALF;
    if (r0 >= N_PTS) return;
    const int r1 = min(r0 + HALF, N_PTS);

    float sum = 0.f;
    int cur = -1;
    for (int r = r0; r < r1; r++) {
        const int s = segid[r];
        if (s != cur) {
            if (cur >= 0) atomicAdd(&g_segsum[cur * DIM + c], sum);
            cur = s; sum = 0.f;
        }
        sum += g_out2[(size_t)r * DIM + c];
    }
    if (cur >= 0) atomicAdd(&g_segsum[cur * DIM + c], sum);

    if (c == 0) {
        int cnt = 0; cur = -1;
        for (int r = r0; r < r1; r++) {
            const int s = segid[r];
            if (s != cur) {
                if (cur >= 0) atomicAdd(&g_segcnt[cur], cnt);
                cur = s; cnt = 0;
            }
            cnt++;
        }
        if (cur >= 0) atomicAdd(&g_segcnt[cur], cnt);
    }
}

__global__ void segmean_kernel() {
    const int t = threadIdx.x;  // 1024 threads
    const int s = t >> 7;
    const float cnt = fmaxf((float)g_segcnt[s], 1.0f);
    g_segmean[t] = g_segsum[t] / cnt;
}

// ---------------- finalize: enc, mid, mid@W3, relu(feats - relu(.+b3)) -----------
// smem: W3s[128][128] | Mt[128][64] | red[256] | rm1s[64]
__global__ void __launch_bounds__(NTHR, 2)
finalize_kernel(const float* __restrict__ feats, const int* __restrict__ segid,
                const float* __restrict__ W3, const float* __restrict__ b3,
                float* __restrict__ out) {
    extern __shared__ char smem_raw[];
    float* W3s  = reinterpret_cast<float*>(smem_raw);  // 128*128
    float* Mt   = W3s + DIM * DIM;                     // 128*64
    float* red  = Mt + DIM * TILE;                     // 256
    float* rm1s = red + NTHR;                          // 64

    const int t = threadIdx.x;
    const int nbase = blockIdx.x * TILE;
    const int gpt = t & 63, gseg = t >> 6;
    const int n = nbase + gpt;

    {   // stage W3
        const float4* Wg = reinterpret_cast<const float4*>(W3);
        float4* Ws4 = reinterpret_cast<float4*>(W3s);
#pragma unroll
        for (int i = 0; i < 16; i++) Ws4[t + i * NTHR] = Wg[t + i * NTHR];
    }

    const float4* o1p = reinterpret_cast<const float4*>(g_out1 + (size_t)n * DIM) + gseg * 8;
    const float4* o2p = reinterpret_cast<const float4*>(g_out2 + (size_t)n * DIM) + gseg * 8;

    float4 v1[8];
    float psum = 0.f;
#pragma unroll
    for (int q = 0; q < 8; q++) {
        v1[q] = o1p[q];
        psum += v1[q].x + v1[q].y + v1[q].z + v1[q].w;
    }
    red[t] = psum;
    __syncthreads();
    if (t < TILE)
        rm1s[t] = (red[t] + red[t + 64] + red[t + 128] + red[t + 192]) * (1.0f / 128.0f);
    __syncthreads();

    const float rm = rm1s[gpt];
    const int sg = segid[n];
    const float4* smn = reinterpret_cast<const float4*>(g_segmean + sg * DIM) + gseg * 8;
#pragma unroll
    for (int q = 0; q < 8; q++) {
        const float4 b = o2p[q];
        const float4 m = smn[q];
        const int d0 = gseg * 32 + q * 4;
        Mt[(d0 + 0) * TILE + gpt] = sqrtf(fmaf(rm, m.x, 1e-12f)) + v1[q].x + b.x;
        Mt[(d0 + 1) * TILE + gpt] = sqrtf(fmaf(rm, m.y, 1e-12f)) + v1[q].y + b.y;
        Mt[(d0 + 2) * TILE + gpt] = sqrtf(fmaf(rm, m.z, 1e-12f)) + v1[q].z + b.z;
        Mt[(d0 + 3) * TILE + gpt] = sqrtf(fmaf(rm, m.w, 1e-12f)) + v1[q].w + b.w;
    }
    __syncthreads();

    const int cx = t & 15, py = t >> 4;
    unsigned long long acc[4][4];
#pragma unroll
    for (int i = 0; i < 4; i++)
#pragma unroll
        for (int j = 0; j < 4; j++) acc[i][j] = 0ULL;

#pragma unroll 4
    for (int d = 0; d < DIM; d++) {
        const float4 g = *reinterpret_cast<const float4*>(&Mt[d * TILE + 4 * py]);
        const ulonglong2 w0 = *reinterpret_cast<const ulonglong2*>(&W3s[d * DIM + 8 * cx]);
        const ulonglong2 w1 = *reinterpret_cast<const ulonglong2*>(&W3s[d * DIM + 8 * cx + 4]);
        const unsigned long long ga = dup2(g.x), gb = dup2(g.y),
                                 gc = dup2(g.z), gd = dup2(g.w);
        fma2(acc[0][0], ga, w0.x); fma2(acc[0][1], ga, w0.y);
        fma2(acc[0][2], ga, w1.x); fma2(acc[0][3], ga, w1.y);
        fma2(acc[1][0], gb, w0.x); fma2(acc[1][1], gb, w0.y);
        fma2(acc[1][2], gb, w1.x); fma2(acc[1][3], gb, w1.y);
        fma2(acc[2][0], gc, w0.x); fma2(acc[2][1], gc, w0.y);
        fma2(acc[2][2], gc, w1.x); fma2(acc[2][3], gc, w1.y);
        fma2(acc[3][0], gd, w0.x); fma2(acc[3][1], gd, w0.y);
        fma2(acc[3][2], gd, w1.x); fma2(acc[3][3], gd, w1.y);
    }

    const float4 bA = *reinterpret_cast<const float4*>(&b3[8 * cx]);
    const float4 bB = *reinterpret_cast<const float4*>(&b3[8 * cx + 4]);
#pragma unroll
    for (int i = 0; i < 4; i++) {
        const int row = nbase + 4 * py + i;
        const float* fp = feats + (size_t)row * DIM + 8 * cx;
        const float4 f0 = *reinterpret_cast<const float4*>(fp);
        const float4 f1 = *reinterpret_cast<const float4*>(fp + 4);
        const float2 a0 = upk(acc[i][0]), a1 = upk(acc[i][1]);
        const float2 a2 = upk(acc[i][2]), a3 = upk(acc[i][3]);
        float4 r0, r1;
        r0.x = fmaxf(f0.x - fmaxf(a0.x + bA.x, 0.f), 0.f);
        r0.y = fmaxf(f0.y - fmaxf(a0.y + bA.y, 0.f), 0.f);
        r0.z = fmaxf(f0.z - fmaxf(a1.x + bA.z, 0.f), 0.f);
        r0.w = fmaxf(f0.w - fmaxf(a1.y + bA.w, 0.f), 0.f);
        r1.x = fmaxf(f1.x - fmaxf(a2.x + bB.x, 0.f), 0.f);
        r1.y = fmaxf(f1.y - fmaxf(a2.y + bB.y, 0.f), 0.f);
        r1.z = fmaxf(f1.z - fmaxf(a3.x + bB.z, 0.f), 0.f);
        r1.w = fmaxf(f1.w - fmaxf(a3.y + bB.w, 0.f), 0.f);
        float* op = out + (size_t)row * DIM + 8 * cx;
        *reinterpret_cast<float4*>(op)     = r0;
        *reinterpret_cast<float4*>(op + 4) = r1;
    }
}

// ---------------- launch ----------------
extern "C" void kernel_launch(void* const* d_in, const int* in_sizes, int n_in,
                              void* d_out, int out_size) {
    const float* feats = (const float*)d_in[0];
    const int* nidx = (const int*)d_in[1];
    const int* nmask = (const int*)d_in[2];   // bool materialized as int32
    const int* segid = (const int*)d_in[3];
    // num_segments may or may not be materialized as an input scalar
    const int o = (n_in >= 11) ? 1 : 0;
    const float* W1 = (const float*)d_in[4 + o];
    const float* b1 = (const float*)d_in[5 + o];
    const float* W2 = (const float*)d_in[6 + o];
    const float* b2 = (const float*)d_in[7 + o];
    const float* W3 = (const float*)d_in[8 + o];
    const float* b3 = (const float*)d_in[9 + o];
    float* out = (float*)d_out;

    const size_t smem_conv = (size_t)(DIM * DIM + DIM * TILE) * 4 +
                             (size_t)TILE * KNB * 4 + (size_t)TILE * KNB;  // 106944
    const size_t smem_fin = (size_t)(DIM * DIM + DIM * TILE + NTHR + TILE) * 4;  // 99584

    cudaFuncSetAttribute(conv_kernel, cudaFuncAttributeMaxDynamicSharedMemorySize,
                         (int)smem_conv);
    cudaFuncSetAttribute(finalize_kernel, cudaFuncAttributeMaxDynamicSharedMemorySize,
                         (int)smem_fin);

    zero_seg_kernel<<<1, 1024>>>();

    dim3 cgrid(N_PTS / TILE, 2, 1);
    conv_kernel<<<cgrid, NTHR, smem_conv>>>(feats, nidx, nmask, W1, b1, W2, b2);

    segreduce_kernel<<<(N_PTS + 511) / 512, 256>>>(segid);
    segmean_kernel<<<1, 1024>>>();

    finalize_kernel<<<N_PTS / TILE, NTHR, smem_fin>>>(feats, segid, W3, b3, out);
}

// round 4
// speedup vs baseline: 4.0149x; 4.0149x over previous
#include <cuda_runtime.h>
#include <cuda_bf16.h>
#include <cstdint>

#define N_PTS 400000
#define DIM   128
#define KNB   27
#define NSEG  8
#define MTILE 128
#define NTHR  256
#define NBLK  (N_PTS / MTILE)
#define FTILE 64

// ---------------- scratch (static device globals: allocation-free) ----------------
__device__ float g_out1[(size_t)N_PTS * DIM];
__device__ float g_out2[(size_t)N_PTS * DIM];
__device__ float g_segsum[NSEG * DIM];
__device__ float g_segmean[NSEG * DIM];
__device__ int   g_segcnt[NSEG];
__device__ __nv_bfloat16 g_fhi[(size_t)N_PTS * DIM];
__device__ __nv_bfloat16 g_flo[(size_t)N_PTS * DIM];
// W images: [k][conv][part(hi/lo)] 32KB tiles, SMEM-image (row-swizzled, ldmatrix-ready)
__device__ __nv_bfloat16 g_Wimg[(size_t)KNB * 2 * 2 * 16384];

// ---------------- smem layout for conv kernel (bytes) ----------------
#define SM_MB   0                               // mbar w1 @0, mbar w2 @8
#define SM_IDX  64
#define SM_MSK  (SM_IDX + MTILE * KNB * 4)      // 13888
#define SM_AHI  17408
#define SM_ALO  (SM_AHI + 32768)                // 50176
#define SM_W1H  (SM_ALO + 32768)                // 82944
#define SM_W1L  (SM_W1H + 32768)                // 115712
#define SM_W2H  (SM_W1L + 32768)                // 148480
#define SM_W2L  (SM_W2H + 32768)                // 181248
#define SM_TOTAL (SM_W2L + 32768)               // 214016

__device__ __forceinline__ uint32_t smem_u32(const void* p) {
    return (uint32_t)__cvta_generic_to_shared(p);
}

// ---------------- PTX helpers (all baseline sm_80/sm_90 features) ----------------
#define MBAR_INIT(a, c) \
    asm volatile("mbarrier.init.shared.b64 [%0], %1;" :: "r"(a), "r"(c) : "memory")
#define MBAR_EXPECT_TX(a, b) \
    asm volatile("mbarrier.arrive.expect_tx.shared.b64 _, [%0], %1;" :: "r"(a), "r"(b) : "memory")
#define MBAR_WAIT(a, ph) do {                                                 \
    uint32_t _m = (a), _p = (ph), _d;                                         \
    asm volatile("{\n .reg .pred p;\n"                                        \
        " mbarrier.try_wait.parity.acquire.cta.shared::cta.b64 p, [%1], %2;\n"\
        " selp.b32 %0, 1, 0, p;\n}" : "=r"(_d) : "r"(_m), "r"(_p) : "memory");\
    if (!_d) {                                                                \
        asm volatile("{\n .reg .pred P1;\n"                                   \
        "W%=:\n mbarrier.try_wait.parity.acquire.cta.shared::cta.b64 P1, [%0], %1, 0x989680;\n" \
        " @P1 bra.uni D%=;\n bra.uni W%=;\nD%=:\n}" :: "r"(_m), "r"(_p) : "memory"); \
    } } while (0)

__device__ __forceinline__ void bulk_g2s(uint32_t dst, const void* src,
                                         uint32_t bytes, uint32_t mbar) {
    asm volatile(
        "cp.async.bulk.shared::cluster.global.mbarrier::complete_tx::bytes "
        "[%0], [%1], %2, [%3];"
        :: "r"(dst), "l"(src), "r"(bytes), "r"(mbar) : "memory");
}
__device__ __forceinline__ void ldsm4(uint32_t* r, uint32_t addr) {
    asm volatile("ldmatrix.sync.aligned.m8n8.x4.shared.b16 {%0,%1,%2,%3}, [%4];"
        : "=r"(r[0]), "=r"(r[1]), "=r"(r[2]), "=r"(r[3]) : "r"(addr));
}
__device__ __forceinline__ void mma_bf16(float* c, const uint32_t* a, const uint32_t* b) {
    asm volatile("mma.sync.aligned.m16n8k16.row.col.f32.bf16.bf16.f32 "
        "{%0,%1,%2,%3}, {%4,%5,%6,%7}, {%8,%9}, {%0,%1,%2,%3};"
        : "+f"(c[0]), "+f"(c[1]), "+f"(c[2]), "+f"(c[3])
        : "r"(a[0]), "r"(a[1]), "r"(a[2]), "r"(a[3]), "r"(b[0]), "r"(b[1]));
}

// ---------------- packed f32x2 helpers (for finalize FFMA2 GEMM) ----------
__device__ __forceinline__ void fma2(unsigned long long& d, unsigned long long a,
                                     unsigned long long b) {
    asm("fma.rn.f32x2 %0, %1, %2, %0;" : "+l"(d) : "l"(a), "l"(b));
}
__device__ __forceinline__ unsigned long long dup2(float x) {
    unsigned long long r;
    asm("mov.b64 %0, {%1, %1};" : "=l"(r) : "f"(x));
    return r;
}
__device__ __forceinline__ float2 upk(unsigned long long v) {
    float2 r;
    asm("mov.b64 {%0, %1}, %2;" : "=f"(r.x), "=f"(r.y) : "l"(v));
    return r;
}
__device__ __forceinline__ uint32_t packbf2(float lo, float hi) {
    uint32_t r;
    asm("cvt.rn.bf16x2.f32 %0, %1, %2;" : "=r"(r) : "f"(hi), "f"(lo));
    return r;
}

// ---------------- pre-pass: split feats into bf16 hi/lo ----------------
__global__ void split_feats_kernel(const float* __restrict__ feats) {
    const size_t i = ((size_t)blockIdx.x * NTHR + threadIdx.x) * 4;
    const float4 v = *reinterpret_cast<const float4*>(feats + i);
    const float hx = __bfloat162float(__float2bfloat16(v.x));
    const float hy = __bfloat162float(__float2bfloat16(v.y));
    const float hz = __bfloat162float(__float2bfloat16(v.z));
    const float hw = __bfloat162float(__float2bfloat16(v.w));
    uint2 hi, lo;
    hi.x = packbf2(v.x, v.y);       hi.y = packbf2(v.z, v.w);
    lo.x = packbf2(v.x - hx, v.y - hy);
    lo.y = packbf2(v.z - hz, v.w - hw);
    *reinterpret_cast<uint2*>(g_fhi + i) = hi;
    *reinterpret_cast<uint2*>(g_flo + i) = lo;
}

// ---------------- pre-pass: W -> transposed, split, SMEM-image layout ----------
// W image tile (32KB) = 128 n-rows x 256B; row n holds 128 bf16 over kdim d,
// 16B chunk c stored at chunk (c ^ (n&7))  [ldmatrix swizzle]
__global__ void prep_w_kernel(const float* __restrict__ W1, const float* __restrict__ W2) {
    const uint32_t t = blockIdx.x * NTHR + threadIdx.x;   // 27*2*128*128 threads
    const uint32_t d = t & 127;
    const uint32_t n = (t >> 7) & 127;
    const uint32_t conv = (t >> 14) & 1;
    const uint32_t k = t >> 15;
    const float w = (conv ? W2 : W1)[((size_t)k * DIM + d) * DIM + n];
    const float hf = __bfloat162float(__float2bfloat16(w));
    const uint32_t off = n * 256 + ((((d >> 3) ^ (n & 7)) << 4)) + (d & 7) * 2;
    const size_t tile = (size_t)((k * 2 + conv) * 2);
    g_Wimg[tile * 16384 + (off >> 1)]       = __float2bfloat16(w);
    g_Wimg[(tile + 1) * 16384 + (off >> 1)] = __float2bfloat16(w - hf);
}

// ---------------- zero segment accumulators ----------------
__global__ void zero_seg_kernel() {
    int t = blockIdx.x * blockDim.x + threadIdx.x;
    if (t < NSEG * DIM) g_segsum[t] = 0.f;
    if (t < NSEG) g_segcnt[t] = 0;
}

// ---------------- A-tile gather stage: row r, part p; swizzled chunks ----------
__device__ __forceinline__ void stage_A(char* smem, const int* idx_s,
                                        const unsigned char* msk_s, int k) {
    const int t = threadIdx.x;
    const int r = t & 127;
    const int p = t >> 7;
    const int id = idx_s[r * KNB + k];
    const bool m = msk_s[r * KNB + k] != 0;
    const __nv_bfloat16* src = (p ? g_flo : g_fhi) + (size_t)id * DIM;
    char* dst = smem + (p ? SM_ALO : SM_AHI) + r * 256;
    const uint32_t x = (uint32_t)(r & 7);
    if (m) {
#pragma unroll
        for (uint32_t c = 0; c < 16; c++) {
            const uint4 v = *reinterpret_cast<const uint4*>(src + c * 8);
            *reinterpret_cast<uint4*>(dst + ((c ^ x) << 4)) = v;
        }
    } else {
        const uint4 z = make_uint4(0, 0, 0, 0);
#pragma unroll
        for (uint32_t c = 0; c < 16; c++)
            *reinterpret_cast<uint4*>(dst + ((c ^ x) << 4)) = z;
    }
}

// ---------------- mma.sync conv: both convs, 128 pts x 128 cols ----------------
__global__ void __launch_bounds__(NTHR, 1)
conv_mma_kernel(const int* __restrict__ nidx, const int* __restrict__ nmask,
                const float* __restrict__ b1, const float* __restrict__ b2) {
    extern __shared__ char smem[];
    const uint32_t sb = smem_u32(smem);
    const int t = threadIdx.x;
    const int lane = t & 31;
    const int wid = t >> 5;
    const int wm = wid >> 2;        // 0..1 : 64-row band
    const int wn = wid & 3;         // 0..3 : 32-col band
    const int nbase = blockIdx.x * MTILE;

    int* idx_s = reinterpret_cast<int*>(smem + SM_IDX);
    unsigned char* msk_s = reinterpret_cast<unsigned char*>(smem + SM_MSK);

    for (int i = t; i < MTILE * KNB; i += NTHR) {
        idx_s[i] = nidx[(size_t)nbase * KNB + i];
        msk_s[i] = (unsigned char)(nmask[(size_t)nbase * KNB + i] != 0);
    }

    const char* wimg = reinterpret_cast<const char*>(g_Wimg);
    if (t == 0) {
        MBAR_INIT(sb + SM_MB, 1);
        MBAR_INIT(sb + SM_MB + 8, 1);
        MBAR_EXPECT_TX(sb + SM_MB, 65536);
        bulk_g2s(sb + SM_W1H, wimg + 0 * 32768, 32768, sb + SM_MB);
        bulk_g2s(sb + SM_W1L, wimg + 1 * 32768, 32768, sb + SM_MB);
        MBAR_EXPECT_TX(sb + SM_MB + 8, 65536);
        bulk_g2s(sb + SM_W2H, wimg + 2 * 32768, 32768, sb + SM_MB + 8);
        bulk_g2s(sb + SM_W2L, wimg + 3 * 32768, 32768, sb + SM_MB + 8);
    }
    __syncthreads();       // idx_s/msk_s visible before first stage_A
    stage_A(smem, idx_s, msk_s, 0);

    // per-thread ldmatrix address components
    const uint32_t a_row = (uint32_t)(wm * 64 + (lane & 15)) * 256;
    const uint32_t b_row = (uint32_t)(wn * 32 + ((lane >> 4) << 3) + (lane & 7)) * 256;
    const uint32_t xr = (uint32_t)(lane & 7);
    const uint32_t ahalf = (uint32_t)(lane >> 4);
    const uint32_t bhalf = (uint32_t)((lane >> 3) & 1);

    float acc[2][4][4][4];
#pragma unroll
    for (int c = 0; c < 2; c++)
#pragma unroll
        for (int i = 0; i < 4; i++)
#pragma unroll
            for (int j = 0; j < 4; j++)
#pragma unroll
                for (int q = 0; q < 4; q++) acc[c][i][j][q] = 0.f;

#pragma unroll 1
    for (int k = 0; k < KNB; k++) {
        const uint32_t ph = (uint32_t)(k & 1);
        __syncthreads();                       // A[k] staged; W reads of k-1 done
        MBAR_WAIT(sb + SM_MB, ph);             // W1[k]
        MBAR_WAIT(sb + SM_MB + 8, ph);         // W2[k]

#pragma unroll 1
        for (uint32_t kc = 0; kc < 8; kc++) {
            const uint32_t ach = ((2 * kc + ahalf) ^ xr) << 4;
            const uint32_t bch = ((2 * kc + bhalf) ^ xr) << 4;
            uint32_t ah[4][4], al[4][4];
#pragma unroll
            for (int i = 0; i < 4; i++)
                ldsm4(ah[i], sb + SM_AHI + a_row + (uint32_t)i * 4096 + ach);
#pragma unroll
            for (int i = 0; i < 4; i++)
                ldsm4(al[i], sb + SM_ALO + a_row + (uint32_t)i * 4096 + ach);
#pragma unroll
            for (int c = 0; c < 2; c++) {
                const uint32_t wH = c ? SM_W2H : SM_W1H;
                const uint32_t wL = c ? SM_W2L : SM_W1L;
                uint32_t wb[8];
                ldsm4(&wb[0], sb + wH + b_row + bch);
                ldsm4(&wb[4], sb + wH + b_row + 4096 + bch);
#pragma unroll
                for (int i = 0; i < 4; i++)
#pragma unroll
                    for (int j = 0; j < 4; j++)
                        mma_bf16(acc[c][i][j], ah[i], &wb[j * 2]);
#pragma unroll
                for (int i = 0; i < 4; i++)
#pragma unroll
                    for (int j = 0; j < 4; j++)
                        mma_bf16(acc[c][i][j], al[i], &wb[j * 2]);
                ldsm4(&wb[0], sb + wL + b_row + bch);
                ldsm4(&wb[4], sb + wL + b_row + 4096 + bch);
#pragma unroll
                for (int i = 0; i < 4; i++)
#pragma unroll
                    for (int j = 0; j < 4; j++)
                        mma_bf16(acc[c][i][j], ah[i], &wb[j * 2]);
            }
        }
        __syncthreads();                       // all reads of A/W for k complete
        if (k < KNB - 1) {
            if (t == 0) {
                const size_t tb = (size_t)(k + 1) * 4 * 32768;
                MBAR_EXPECT_TX(sb + SM_MB, 65536);
                bulk_g2s(sb + SM_W1H, wimg + tb, 32768, sb + SM_MB);
                bulk_g2s(sb + SM_W1L, wimg + tb + 32768, 32768, sb + SM_MB);
                MBAR_EXPECT_TX(sb + SM_MB + 8, 65536);
                bulk_g2s(sb + SM_W2H, wimg + tb + 65536, 32768, sb + SM_MB + 8);
                bulk_g2s(sb + SM_W2L, wimg + tb + 98304, 32768, sb + SM_MB + 8);
            }
            stage_A(smem, idx_s, msk_s, k + 1);
        }
    }

    // epilogue: +bias, relu, store fp32
    const int g = lane >> 2, tig = lane & 3;
#pragma unroll
    for (int c = 0; c < 2; c++) {
        float* outp = c ? g_out2 : g_out1;
        const float* bias = c ? b2 : b1;
#pragma unroll
        for (int j = 0; j < 4; j++) {
            const int col = wn * 32 + j * 8 + tig * 2;
            const float2 bv = *reinterpret_cast<const float2*>(bias + col);
#pragma unroll
            for (int i = 0; i < 4; i++) {
                const int row0 = nbase + wm * 64 + i * 16 + g;
                float2 v0, v1;
                v0.x = fmaxf(acc[c][i][j][0] + bv.x, 0.f);
                v0.y = fmaxf(acc[c][i][j][1] + bv.y, 0.f);
                v1.x = fmaxf(acc[c][i][j][2] + bv.x, 0.f);
                v1.y = fmaxf(acc[c][i][j][3] + bv.y, 0.f);
                *reinterpret_cast<float2*>(outp + (size_t)row0 * DIM + col) = v0;
                *reinterpret_cast<float2*>(outp + (size_t)(row0 + 8) * DIM + col) = v1;
            }
        }
    }
}

// ---------------- segment sums of out2 (+counts); segment_ids sorted ----------
__global__ void segreduce_kernel(const int* __restrict__ segid) {
    const int RPB = 512, HALF = 256;
    const int c = threadIdx.x & 127;
    const int h = threadIdx.x >> 7;
    const int r0 = blockIdx.x * RPB + h * HALF;
    if (r0 >= N_PTS) return;
    const int r1 = min(r0 + HALF, N_PTS);

    float sum = 0.f;
    int cur = -1;
    for (int r = r0; r < r1; r++) {
        const int s = segid[r];
        if (s != cur) {
            if (cur >= 0) atomicAdd(&g_segsum[cur * DIM + c], sum);
            cur = s; sum = 0.f;
        }
        sum += g_out2[(size_t)r * DIM + c];
    }
    if (cur >= 0) atomicAdd(&g_segsum[cur * DIM + c], sum);

    if (c == 0) {
        int cnt = 0; cur = -1;
        for (int r = r0; r < r1; r++) {
            const int s = segid[r];
            if (s != cur) {
                if (cur >= 0) atomicAdd(&g_segcnt[cur], cnt);
                cur = s; cnt = 0;
            }
            cnt++;
        }
        if (cur >= 0) atomicAdd(&g_segcnt[cur], cnt);
    }
}

__global__ void segmean_kernel() {
    const int t = threadIdx.x;  // 1024 threads
    const int s = t >> 7;
    const float cnt = fmaxf((float)g_segcnt[s], 1.0f);
    g_segmean[t] = g_segsum[t] / cnt;
}

// ---------------- finalize: enc, mid, mid@W3, relu(feats - relu(.+b3)) -----------
__global__ void __launch_bounds__(NTHR, 2)
finalize_kernel(const float* __restrict__ feats, const int* __restrict__ segid,
                const float* __restrict__ W3, const float* __restrict__ b3,
                float* __restrict__ out) {
    extern __shared__ char smem_raw[];
    float* W3s  = reinterpret_cast<float*>(smem_raw);  // 128*128
    float* Mt   = W3s + DIM * DIM;                     // 128*64
    float* red  = Mt + DIM * FTILE;                    // 256
    float* rm1s = red + NTHR;                          // 64

    const int t = threadIdx.x;
    const int nbase = blockIdx.x * FTILE;
    const int gpt = t & 63, gseg = t >> 6;
    const int n = nbase + gpt;

    {   // stage W3
        const float4* Wg = reinterpret_cast<const float4*>(W3);
        float4* Ws4 = reinterpret_cast<float4*>(W3s);
#pragma unroll
        for (int i = 0; i < 16; i++) Ws4[t + i * NTHR] = Wg[t + i * NTHR];
    }

    const float4* o1p = reinterpret_cast<const float4*>(g_out1 + (size_t)n * DIM) + gseg * 8;
    const float4* o2p = reinterpret_cast<const float4*>(g_out2 + (size_t)n * DIM) + gseg * 8;

    float4 v1[8];
    float psum = 0.f;
#pragma unroll
    for (int q = 0; q < 8; q++) {
        v1[q] = o1p[q];
        psum += v1[q].x + v1[q].y + v1[q].z + v1[q].w;
    }
    red[t] = psum;
    __syncthreads();
    if (t < FTILE)
        rm1s[t] = (red[t] + red[t + 64] + red[t + 128] + red[t + 192]) * (1.0f / 128.0f);
    __syncthreads();

    const float rm = rm1s[gpt];
    const int sg = segid[n];
    const float4* smn = reinterpret_cast<const float4*>(g_segmean + sg * DIM) + gseg * 8;
#pragma unroll
    for (int q = 0; q < 8; q++) {
        const float4 b = o2p[q];
        const float4 m = smn[q];
        const int d0 = gseg * 32 + q * 4;
        Mt[(d0 + 0) * FTILE + gpt] = sqrtf(fmaf(rm, m.x, 1e-12f)) + v1[q].x + b.x;
        Mt[(d0 + 1) * FTILE + gpt] = sqrtf(fmaf(rm, m.y, 1e-12f)) + v1[q].y + b.y;
        Mt[(d0 + 2) * FTILE + gpt] = sqrtf(fmaf(rm, m.z, 1e-12f)) + v1[q].z + b.z;
        Mt[(d0 + 3) * FTILE + gpt] = sqrtf(fmaf(rm, m.w, 1e-12f)) + v1[q].w + b.w;
    }
    __syncthreads();

    const int cx = t & 15, py = t >> 4;
    unsigned long long acc[4][4];
#pragma unroll
    for (int i = 0; i < 4; i++)
#pragma unroll
        for (int j = 0; j < 4; j++) acc[i][j] = 0ULL;

#pragma unroll 4
    for (int d = 0; d < DIM; d++) {
        const float4 g = *reinterpret_cast<const float4*>(&Mt[d * FTILE + 4 * py]);
        const ulonglong2 w0 = *reinterpret_cast<const ulonglong2*>(&W3s[d * DIM + 8 * cx]);
        const ulonglong2 w1 = *reinterpret_cast<const ulonglong2*>(&W3s[d * DIM + 8 * cx + 4]);
        const unsigned long long ga = dup2(g.x), gb = dup2(g.y),
                                 gc = dup2(g.z), gd = dup2(g.w);
        fma2(acc[0][0], ga, w0.x); fma2(acc[0][1], ga, w0.y);
        fma2(acc[0][2], ga, w1.x); fma2(acc[0][3], ga, w1.y);
        fma2(acc[1][0], gb, w0.x); fma2(acc[1][1], gb, w0.y);
        fma2(acc[1][2], gb, w1.x); fma2(acc[1][3], gb, w1.y);
        fma2(acc[2][0], gc, w0.x); fma2(acc[2][1], gc, w0.y);
        fma2(acc[2][2], gc, w1.x); fma2(acc[2][3], gc, w1.y);
        fma2(acc[3][0], gd, w0.x); fma2(acc[3][1], gd, w0.y);
        fma2(acc[3][2], gd, w1.x); fma2(acc[3][3], gd, w1.y);
    }

    const float4 bA = *reinterpret_cast<const float4*>(&b3[8 * cx]);
    const float4 bB = *reinterpret_cast<const float4*>(&b3[8 * cx + 4]);
#pragma unroll
    for (int i = 0; i < 4; i++) {
        const int row = nbase + 4 * py + i;
        const float* fp = feats + (size_t)row * DIM + 8 * cx;
        const float4 f0 = *reinterpret_cast<const float4*>(fp);
        const float4 f1 = *reinterpret_cast<const float4*>(fp + 4);
        const float2 a0 = upk(acc[i][0]), a1 = upk(acc[i][1]);
        const float2 a2 = upk(acc[i][2]), a3 = upk(acc[i][3]);
        float4 r0, r1;
        r0.x = fmaxf(f0.x - fmaxf(a0.x + bA.x, 0.f), 0.f);
        r0.y = fmaxf(f0.y - fmaxf(a0.y + bA.y, 0.f), 0.f);
        r0.z = fmaxf(f0.z - fmaxf(a1.x + bA.z, 0.f), 0.f);
        r0.w = fmaxf(f0.w - fmaxf(a1.y + bA.w, 0.f), 0.f);
        r1.x = fmaxf(f1.x - fmaxf(a2.x + bB.x, 0.f), 0.f);
        r1.y = fmaxf(f1.y - fmaxf(a2.y + bB.y, 0.f), 0.f);
        r1.z = fmaxf(f1.z - fmaxf(a3.x + bB.z, 0.f), 0.f);
        r1.w = fmaxf(f1.w - fmaxf(a3.y + bB.w, 0.f), 0.f);
        float* op = out + (size_t)row * DIM + 8 * cx;
        *reinterpret_cast<float4*>(op)     = r0;
        *reinterpret_cast<float4*>(op + 4) = r1;
    }
}

// ---------------- launch ----------------
extern "C" void kernel_launch(void* const* d_in, const int* in_sizes, int n_in,
                              void* d_out, int out_size) {
    const float* feats = (const float*)d_in[0];
    const int* nidx = (const int*)d_in[1];
    const int* nmask = (const int*)d_in[2];   // bool materialized as int32
    const int* segid = (const int*)d_in[3];
    const int o = (n_in >= 11) ? 1 : 0;
    const float* W1 = (const float*)d_in[4 + o];
    const float* b1 = (const float*)d_in[5 + o];
    const float* W2 = (const float*)d_in[6 + o];
    const float* b2 = (const float*)d_in[7 + o];
    const float* W3 = (const float*)d_in[8 + o];
    const float* b3 = (const float*)d_in[9 + o];
    float* out = (float*)d_out;

    const size_t smem_fin = (size_t)(DIM * DIM + DIM * FTILE + NTHR + FTILE) * 4;

    cudaFuncSetAttribute(conv_mma_kernel, cudaFuncAttributeMaxDynamicSharedMemorySize,
                         SM_TOTAL);
    cudaFuncSetAttribute(finalize_kernel, cudaFuncAttributeMaxDynamicSharedMemorySize,
                         (int)smem_fin);

    split_feats_kernel<<<(N_PTS * DIM) / (NTHR * 4), NTHR>>>(feats);
    prep_w_kernel<<<(KNB * 2 * DIM * DIM) / NTHR, NTHR>>>(W1, W2);
    zero_seg_kernel<<<1, 1024>>>();

    conv_mma_kernel<<<NBLK, NTHR, SM_TOTAL>>>(nidx, nmask, b1, b2);

    segreduce_kernel<<<(N_PTS + 511) / 512, 256>>>(segid);
    segmean_kernel<<<1, 1024>>>();

    finalize_kernel<<<N_PTS / FTILE, NTHR, smem_fin>>>(feats, segid, W3, b3, out);
}

// round 5
// speedup vs baseline: 4.5608x; 1.1360x over previous
#include <cuda_runtime.h>
#include <cuda_bf16.h>
#include <cstdint>

#define N_PTS 400000
#define DIM   128
#define KNB   27
#define NSEG  8
#define MTILE 128
#define CTHR  512
#define NTHR  256
#define NBLK  (N_PTS / MTILE)
#define FTILE 64

// ---------------- scratch (static device globals: allocation-free) ----------------
__device__ float g_out1[(size_t)N_PTS * DIM];
__device__ float g_out2[(size_t)N_PTS * DIM];
__device__ float g_segsum[NSEG * DIM];
__device__ float g_segmean[NSEG * DIM];
__device__ int   g_segcnt[NSEG];
__device__ __nv_bfloat16 g_fhi[(size_t)N_PTS * DIM];
__device__ __nv_bfloat16 g_flo[(size_t)N_PTS * DIM];
// W images: [k][conv][part(hi/lo)] 32KB tiles, SMEM-image (row-swizzled, ldmatrix-ready)
__device__ __nv_bfloat16 g_Wimg[(size_t)KNB * 2 * 2 * 16384];

// ---------------- smem layout for conv kernel (bytes) ----------------
#define SM_MB   0          // mbars: W1H@0 W1L@8 W2H@16 W2L@24
#define SM_IDX  64
#define SM_MSK  (SM_IDX + MTILE * KNB * 4)      // 13888
#define SM_AHI  17408
#define SM_ALO  (SM_AHI + 32768)                // 50176
#define SM_W1H  (SM_ALO + 32768)                // 82944
#define SM_W1L  (SM_W1H + 32768)                // 115712
#define SM_W2H  (SM_W1L + 32768)                // 148480
#define SM_W2L  (SM_W2H + 32768)                // 181248
#define SM_TOTAL (SM_W2L + 32768)               // 214016

__device__ __forceinline__ uint32_t smem_u32(const void* p) {
    return (uint32_t)__cvta_generic_to_shared(p);
}

// ---------------- PTX helpers (baseline sm_80/sm_90 features only) ----------------
#define MBAR_INIT(a, c) \
    asm volatile("mbarrier.init.shared.b64 [%0], %1;" :: "r"(a), "r"(c) : "memory")
#define MBAR_EXPECT_TX(a, b) \
    asm volatile("mbarrier.arrive.expect_tx.shared.b64 _, [%0], %1;" :: "r"(a), "r"(b) : "memory")
#define MBAR_WAIT(a, ph) do {                                                 \
    uint32_t _m = (a), _p = (ph), _d;                                         \
    asm volatile("{\n .reg .pred p;\n"                                        \
        " mbarrier.try_wait.parity.acquire.cta.shared::cta.b64 p, [%1], %2;\n"\
        " selp.b32 %0, 1, 0, p;\n}" : "=r"(_d) : "r"(_m), "r"(_p) : "memory");\
    if (!_d) {                                                                \
        asm volatile("{\n .reg .pred P1;\n"                                   \
        "W%=:\n mbarrier.try_wait.parity.acquire.cta.shared::cta.b64 P1, [%0], %1, 0x989680;\n" \
        " @P1 bra.uni D%=;\n bra.uni W%=;\nD%=:\n}" :: "r"(_m), "r"(_p) : "memory"); \
    } } while (0)

#define CP_COMMIT() asm volatile("cp.async.commit_group;" ::: "memory")
#define CP_WAIT(n)  asm volatile("cp.async.wait_group %0;" :: "n"(n) : "memory")

__device__ __forceinline__ void cp16z(uint32_t dst, const void* src, uint32_t srcsz) {
    asm volatile("cp.async.cg.shared.global [%0], [%1], 16, %2;"
                 :: "r"(dst), "l"(src), "r"(srcsz) : "memory");
}
__device__ __forceinline__ void bulk_g2s(uint32_t dst, const void* src,
                                         uint32_t bytes, uint32_t mbar) {
    asm volatile(
        "cp.async.bulk.shared::cluster.global.mbarrier::complete_tx::bytes "
        "[%0], [%1], %2, [%3];"
        :: "r"(dst), "l"(src), "r"(bytes), "r"(mbar) : "memory");
}
__device__ __forceinline__ void ldsm4(uint32_t* r, uint32_t addr) {
    asm volatile("ldmatrix.sync.aligned.m8n8.x4.shared.b16 {%0,%1,%2,%3}, [%4];"
        : "=r"(r[0]), "=r"(r[1]), "=r"(r[2]), "=r"(r[3]) : "r"(addr));
}
__device__ __forceinline__ void mma_bf16(float* c, const uint32_t* a, const uint32_t* b) {
    asm volatile("mma.sync.aligned.m16n8k16.row.col.f32.bf16.bf16.f32 "
        "{%0,%1,%2,%3}, {%4,%5,%6,%7}, {%8,%9}, {%0,%1,%2,%3};"
        : "+f"(c[0]), "+f"(c[1]), "+f"(c[2]), "+f"(c[3])
        : "r"(a[0]), "r"(a[1]), "r"(a[2]), "r"(a[3]), "r"(b[0]), "r"(b[1]));
}

// ---------------- packed f32x2 helpers (for finalize FFMA2 GEMM) ----------
__device__ __forceinline__ void fma2(unsigned long long& d, unsigned long long a,
                                     unsigned long long b) {
    asm("fma.rn.f32x2 %0, %1, %2, %0;" : "+l"(d) : "l"(a), "l"(b));
}
__device__ __forceinline__ unsigned long long dup2(float x) {
    unsigned long long r;
    asm("mov.b64 %0, {%1, %1};" : "=l"(r) : "f"(x));
    return r;
}
__device__ __forceinline__ float2 upk(unsigned long long v) {
    float2 r;
    asm("mov.b64 {%0, %1}, %2;" : "=f"(r.x), "=f"(r.y) : "l"(v));
    return r;
}
__device__ __forceinline__ uint32_t packbf2(float lo, float hi) {
    uint32_t r;
    asm("cvt.rn.bf16x2.f32 %0, %1, %2;" : "=r"(r) : "f"(hi), "f"(lo));
    return r;
}

// ---------------- pre-pass: split feats into bf16 hi/lo ----------------
__global__ void split_feats_kernel(const float* __restrict__ feats) {
    const size_t i = ((size_t)blockIdx.x * NTHR + threadIdx.x) * 4;
    const float4 v = *reinterpret_cast<const float4*>(feats + i);
    const float hx = __bfloat162float(__float2bfloat16(v.x));
    const float hy = __bfloat162float(__float2bfloat16(v.y));
    const float hz = __bfloat162float(__float2bfloat16(v.z));
    const float hw = __bfloat162float(__float2bfloat16(v.w));
    uint2 hi, lo;
    hi.x = packbf2(v.x, v.y);       hi.y = packbf2(v.z, v.w);
    lo.x = packbf2(v.x - hx, v.y - hy);
    lo.y = packbf2(v.z - hz, v.w - hw);
    *reinterpret_cast<uint2*>(g_fhi + i) = hi;
    *reinterpret_cast<uint2*>(g_flo + i) = lo;
}

// ---------------- pre-pass: W -> transposed, split, SMEM-image layout ----------
__global__ void prep_w_kernel(const float* __restrict__ W1, const float* __restrict__ W2) {
    const uint32_t t = blockIdx.x * NTHR + threadIdx.x;   // 27*2*128*128 threads
    const uint32_t d = t & 127;
    const uint32_t n = (t >> 7) & 127;
    const uint32_t conv = (t >> 14) & 1;
    const uint32_t k = t >> 15;
    const float w = (conv ? W2 : W1)[((size_t)k * DIM + d) * DIM + n];
    const float hf = __bfloat162float(__float2bfloat16(w));
    const uint32_t off = n * 256 + ((((d >> 3) ^ (n & 7)) << 4)) + (d & 7) * 2;
    const size_t tile = (size_t)((k * 2 + conv) * 2);
    g_Wimg[tile * 16384 + (off >> 1)]       = __float2bfloat16(w);
    g_Wimg[(tile + 1) * 16384 + (off >> 1)] = __float2bfloat16(w - hf);
}

// ---------------- zero segment accumulators ----------------
__global__ void zero_seg_kernel() {
    int t = blockIdx.x * blockDim.x + threadIdx.x;
    if (t < NSEG * DIM) g_segsum[t] = 0.f;
    if (t < NSEG) g_segcnt[t] = 0;
}

// ---------------- A staging via cp.async zfill (512 threads, 32KB/part) ----------
__device__ __forceinline__ void stage_A_cp(uint32_t sb, uint32_t a_base,
                                           const __nv_bfloat16* fsrc,
                                           const int* idx_s,
                                           const unsigned char* msk_s, int k) {
    const int t = threadIdx.x;
    const int r = t >> 2;                  // row 0..127
    const int q = t & 3;                   // 4 chunks per thread
    const int id = idx_s[r * KNB + k];
    const uint32_t sz = msk_s[r * KNB + k] ? 16u : 0u;
    const char* src = reinterpret_cast<const char*>(fsrc + (size_t)id * DIM) + q * 64;
    const uint32_t drow = sb + a_base + (uint32_t)r * 256;
    const uint32_t x = (uint32_t)(r & 7);
#pragma unroll
    for (int c2 = 0; c2 < 4; c2++) {
        const uint32_t c = (uint32_t)(q * 4 + c2);
        cp16z(drow + ((c ^ x) << 4), src + c2 * 16, sz);
    }
}

// ---------------- MMA product groups ----------------
// warp tile 32(m) x 32(n); acc[i<2][j<4][4]
__device__ __forceinline__ void mma_group1(uint32_t sb, uint32_t a_base, uint32_t w_base,
                                           float acc[2][4][4],
                                           uint32_t a_row, uint32_t b_row,
                                           uint32_t ahalf, uint32_t bhalf, uint32_t xr) {
#pragma unroll
    for (uint32_t kc = 0; kc < 8; kc++) {
        const uint32_t ach = ((2 * kc + ahalf) ^ xr) << 4;
        const uint32_t bch = ((2 * kc + bhalf) ^ xr) << 4;
        uint32_t a0[4], a1[4], wb[8];
        ldsm4(a0, sb + a_base + a_row + ach);
        ldsm4(a1, sb + a_base + a_row + 4096 + ach);
        ldsm4(&wb[0], sb + w_base + b_row + bch);
        ldsm4(&wb[4], sb + w_base + b_row + 4096 + bch);
#pragma unroll
        for (int j = 0; j < 4; j++) {
            mma_bf16(acc[0][j], a0, &wb[j * 2]);
            mma_bf16(acc[1][j], a1, &wb[j * 2]);
        }
    }
}
__device__ __forceinline__ void mma_group2(uint32_t sb, uint32_t a_base,
                                           uint32_t wh_base, uint32_t wl_base,
                                           float acc[2][4][4],
                                           uint32_t a_row, uint32_t b_row,
                                           uint32_t ahalf, uint32_t bhalf, uint32_t xr) {
#pragma unroll
    for (uint32_t kc = 0; kc < 8; kc++) {
        const uint32_t ach = ((2 * kc + ahalf) ^ xr) << 4;
        const uint32_t bch = ((2 * kc + bhalf) ^ xr) << 4;
        uint32_t a0[4], a1[4], wb[8];
        ldsm4(a0, sb + a_base + a_row + ach);
        ldsm4(a1, sb + a_base + a_row + 4096 + ach);
        ldsm4(&wb[0], sb + wh_base + b_row + bch);
        ldsm4(&wb[4], sb + wh_base + b_row + 4096 + bch);
#pragma unroll
        for (int j = 0; j < 4; j++) {
            mma_bf16(acc[0][j], a0, &wb[j * 2]);
            mma_bf16(acc[1][j], a1, &wb[j * 2]);
        }
        ldsm4(&wb[0], sb + wl_base + b_row + bch);
        ldsm4(&wb[4], sb + wl_base + b_row + 4096 + bch);
#pragma unroll
        for (int j = 0; j < 4; j++) {
            mma_bf16(acc[0][j], a0, &wb[j * 2]);
            mma_bf16(acc[1][j], a1, &wb[j * 2]);
        }
    }
}

// ---------------- conv kernel: phased single-buffered pipeline ----------------
__global__ void __launch_bounds__(CTHR, 1)
conv_mma_kernel(const int* __restrict__ nidx, const int* __restrict__ nmask,
                const float* __restrict__ b1, const float* __restrict__ b2) {
    extern __shared__ char smem[];
    const uint32_t sb = smem_u32(smem);
    const int t = threadIdx.x;
    const int lane = t & 31;
    const int wid = t >> 5;
    const int wm = wid >> 2;        // 0..3 : 32-row band
    const int wn = wid & 3;         // 0..3 : 32-col band
    const int nbase = blockIdx.x * MTILE;

    int* idx_s = reinterpret_cast<int*>(smem + SM_IDX);
    unsigned char* msk_s = reinterpret_cast<unsigned char*>(smem + SM_MSK);

    for (int i = t; i < MTILE * KNB; i += CTHR) {
        idx_s[i] = nidx[(size_t)nbase * KNB + i];
        msk_s[i] = (unsigned char)(nmask[(size_t)nbase * KNB + i] != 0);
    }

    const char* wimg = reinterpret_cast<const char*>(g_Wimg);
    if (t == 0) {
        MBAR_INIT(sb + SM_MB, 1);       // W1H
        MBAR_INIT(sb + SM_MB + 8, 1);   // W1L
        MBAR_INIT(sb + SM_MB + 16, 1);  // W2H
        MBAR_INIT(sb + SM_MB + 24, 1);  // W2L
        MBAR_EXPECT_TX(sb + SM_MB, 32768);
        bulk_g2s(sb + SM_W1H, wimg + 0 * 32768, 32768, sb + SM_MB);
        MBAR_EXPECT_TX(sb + SM_MB + 8, 32768);
        bulk_g2s(sb + SM_W1L, wimg + 1 * 32768, 32768, sb + SM_MB + 8);
        MBAR_EXPECT_TX(sb + SM_MB + 16, 32768);
        bulk_g2s(sb + SM_W2H, wimg + 2 * 32768, 32768, sb + SM_MB + 16);
        MBAR_EXPECT_TX(sb + SM_MB + 24, 32768);
        bulk_g2s(sb + SM_W2L, wimg + 3 * 32768, 32768, sb + SM_MB + 24);
    }
    __syncthreads();   // idx_s/msk_s + mbar init visible
    stage_A_cp(sb, SM_ALO, g_flo, idx_s, msk_s, 0);
    CP_COMMIT();
    stage_A_cp(sb, SM_AHI, g_fhi, idx_s, msk_s, 0);
    CP_COMMIT();

    // per-thread ldmatrix address components
    const uint32_t a_row = (uint32_t)(wm * 32 + (lane & 15)) * 256;
    const uint32_t b_row = (uint32_t)(wn * 32 + ((lane >> 4) << 3) + (lane & 7)) * 256;
    const uint32_t xr = (uint32_t)(lane & 7);
    const uint32_t ahalf = (uint32_t)(lane >> 4);
    const uint32_t bhalf = (uint32_t)((lane >> 3) & 1);

    float acc[2][2][4][4];
#pragma unroll
    for (int c = 0; c < 2; c++)
#pragma unroll
        for (int i = 0; i < 2; i++)
#pragma unroll
            for (int j = 0; j < 4; j++)
#pragma unroll
                for (int q = 0; q < 4; q++) acc[c][i][j][q] = 0.f;

#pragma unroll 1
    for (int k = 0; k < KNB; k++) {
        const uint32_t ph = (uint32_t)(k & 1);
        const bool nxt = (k < KNB - 1);

        // ---- g1: Alo x W1hi ----
        CP_WAIT(1);                // Alo[k] done (own)
        __syncthreads();           // B1: Alo visible to all
        MBAR_WAIT(sb + SM_MB, ph); // W1H[k]
        mma_group1(sb, SM_ALO, SM_W1H, acc[0], a_row, b_row, ahalf, bhalf, xr);

        // ---- g23: Ahi x (W1hi, W1lo) ----
        CP_WAIT(0);                // Ahi[k] done (own)
        __syncthreads();           // B2: Ahi visible
        MBAR_WAIT(sb + SM_MB + 8, ph); // W1L[k]
        mma_group2(sb, SM_AHI, SM_W1H, SM_W1L, acc[0], a_row, b_row, ahalf, bhalf, xr);
        __syncthreads();           // B3: W1H/W1L dead
        if (nxt && t == 0) {
            const size_t tb = (size_t)(k + 1) * 4 * 32768;
            MBAR_EXPECT_TX(sb + SM_MB, 32768);
            bulk_g2s(sb + SM_W1H, wimg + tb, 32768, sb + SM_MB);
            MBAR_EXPECT_TX(sb + SM_MB + 8, 32768);
            bulk_g2s(sb + SM_W1L, wimg + tb + 32768, 32768, sb + SM_MB + 8);
        }

        // ---- g4: Alo x W2hi ----
        MBAR_WAIT(sb + SM_MB + 16, ph); // W2H[k]
        mma_group1(sb, SM_ALO, SM_W2H, acc[1], a_row, b_row, ahalf, bhalf, xr);
        __syncthreads();           // B4: Alo dead
        if (nxt) stage_A_cp(sb, SM_ALO, g_flo, idx_s, msk_s, k + 1);
        CP_COMMIT();

        // ---- g56: Ahi x (W2hi, W2lo) ----
        MBAR_WAIT(sb + SM_MB + 24, ph); // W2L[k]
        mma_group2(sb, SM_AHI, SM_W2H, SM_W2L, acc[1], a_row, b_row, ahalf, bhalf, xr);
        __syncthreads();           // B5: W2H/W2L + Ahi dead
        if (nxt && t == 0) {
            const size_t tb = (size_t)(k + 1) * 4 * 32768;
            MBAR_EXPECT_TX(sb + SM_MB + 16, 32768);
            bulk_g2s(sb + SM_W2H, wimg + tb + 65536, 32768, sb + SM_MB + 16);
            MBAR_EXPECT_TX(sb + SM_MB + 24, 32768);
            bulk_g2s(sb + SM_W2L, wimg + tb + 98304, 32768, sb + SM_MB + 24);
        }
        if (nxt) stage_A_cp(sb, SM_AHI, g_fhi, idx_s, msk_s, k + 1);
        CP_COMMIT();
    }

    // epilogue: +bias, relu, store fp32
    const int g = lane >> 2, tig = lane & 3;
#pragma unroll
    for (int c = 0; c < 2; c++) {
        float* outp = c ? g_out2 : g_out1;
        const float* bias = c ? b2 : b1;
#pragma unroll
        for (int j = 0; j < 4; j++) {
            const int col = wn * 32 + j * 8 + tig * 2;
            const float2 bv = *reinterpret_cast<const float2*>(bias + col);
#pragma unroll
            for (int i = 0; i < 2; i++) {
                const int row0 = nbase + wm * 32 + i * 16 + g;
                float2 v0, v1;
                v0.x = fmaxf(acc[c][i][j][0] + bv.x, 0.f);
                v0.y = fmaxf(acc[c][i][j][1] + bv.y, 0.f);
                v1.x = fmaxf(acc[c][i][j][2] + bv.x, 0.f);
                v1.y = fmaxf(acc[c][i][j][3] + bv.y, 0.f);
                *reinterpret_cast<float2*>(outp + (size_t)row0 * DIM + col) = v0;
                *reinterpret_cast<float2*>(outp + (size_t)(row0 + 8) * DIM + col) = v1;
            }
        }
    }
}

// ---------------- segment sums of out2 (+counts); segment_ids sorted ----------
__global__ void segreduce_kernel(const int* __restrict__ segid) {
    const int RPB = 512, HALF = 256;
    const int c = threadIdx.x & 127;
    const int h = threadIdx.x >> 7;
    const int r0 = blockIdx.x * RPB + h * HALF;
    if (r0 >= N_PTS) return;
    const int r1 = min(r0 + HALF, N_PTS);

    float sum = 0.f;
    int cur = -1;
    for (int r = r0; r < r1; r++) {
        const int s = segid[r];
        if (s != cur) {
            if (cur >= 0) atomicAdd(&g_segsum[cur * DIM + c], sum);
            cur = s; sum = 0.f;
        }
        sum += g_out2[(size_t)r * DIM + c];
    }
    if (cur >= 0) atomicAdd(&g_segsum[cur * DIM + c], sum);

    if (c == 0) {
        int cnt = 0; cur = -1;
        for (int r = r0; r < r1; r++) {
            const int s = segid[r];
            if (s != cur) {
                if (cur >= 0) atomicAdd(&g_segcnt[cur], cnt);
                cur = s; cnt = 0;
            }
            cnt++;
        }
        if (cur >= 0) atomicAdd(&g_segcnt[cur], cnt);
    }
}

__global__ void segmean_kernel() {
    const int t = threadIdx.x;  // 1024 threads
    const int s = t >> 7;
    const float cnt = fmaxf((float)g_segcnt[s], 1.0f);
    g_segmean[t] = g_segsum[t] / cnt;
}

// ---------------- finalize: enc, mid, mid@W3, relu(feats - relu(.+b3)) -----------
__global__ void __launch_bounds__(NTHR, 2)
finalize_kernel(const float* __restrict__ feats, const int* __restrict__ segid,
                const float* __restrict__ W3, const float* __restrict__ b3,
                float* __restrict__ out) {
    extern __shared__ char smem_raw[];
    float* W3s  = reinterpret_cast<float*>(smem_raw);  // 128*128
    float* Mt   = W3s + DIM * DIM;                     // 128*64
    float* red  = Mt + DIM * FTILE;                    // 256
    float* rm1s = red + NTHR;                          // 64

    const int t = threadIdx.x;
    const int nbase = blockIdx.x * FTILE;
    const int gpt = t & 63, gseg = t >> 6;
    const int n = nbase + gpt;

    {   // stage W3
        const float4* Wg = reinterpret_cast<const float4*>(W3);
        float4* Ws4 = reinterpret_cast<float4*>(W3s);
#pragma unroll
        for (int i = 0; i < 16; i++) Ws4[t + i * NTHR] = Wg[t + i * NTHR];
    }

    const float4* o1p = reinterpret_cast<const float4*>(g_out1 + (size_t)n * DIM) + gseg * 8;
    const float4* o2p = reinterpret_cast<const float4*>(g_out2 + (size_t)n * DIM) + gseg * 8;

    float4 v1[8];
    float psum = 0.f;
#pragma unroll
    for (int q = 0; q < 8; q++) {
        v1[q] = o1p[q];
        psum += v1[q].x + v1[q].y + v1[q].z + v1[q].w;
    }
    red[t] = psum;
    __syncthreads();
    if (t < FTILE)
        rm1s[t] = (red[t] + red[t + 64] + red[t + 128] + red[t + 192]) * (1.0f / 128.0f);
    __syncthreads();

    const float rm = rm1s[gpt];
    const int sg = segid[n];
    const float4* smn = reinterpret_cast<const float4*>(g_segmean + sg * DIM) + gseg * 8;
#pragma unroll
    for (int q = 0; q < 8; q++) {
        const float4 b = o2p[q];
        const float4 m = smn[q];
        const int d0 = gseg * 32 + q * 4;
        Mt[(d0 + 0) * FTILE + gpt] = sqrtf(fmaf(rm, m.x, 1e-12f)) + v1[q].x + b.x;
        Mt[(d0 + 1) * FTILE + gpt] = sqrtf(fmaf(rm, m.y, 1e-12f)) + v1[q].y + b.y;
        Mt[(d0 + 2) * FTILE + gpt] = sqrtf(fmaf(rm, m.z, 1e-12f)) + v1[q].z + b.z;
        Mt[(d0 + 3) * FTILE + gpt] = sqrtf(fmaf(rm, m.w, 1e-12f)) + v1[q].w + b.w;
    }
    __syncthreads();

    const int cx = t & 15, py = t >> 4;
    unsigned long long acc[4][4];
#pragma unroll
    for (int i = 0; i < 4; i++)
#pragma unroll
        for (int j = 0; j < 4; j++) acc[i][j] = 0ULL;

#pragma unroll 4
    for (int d = 0; d < DIM; d++) {
        const float4 g = *reinterpret_cast<const float4*>(&Mt[d * FTILE + 4 * py]);
        const ulonglong2 w0 = *reinterpret_cast<const ulonglong2*>(&W3s[d * DIM + 8 * cx]);
        const ulonglong2 w1 = *reinterpret_cast<const ulonglong2*>(&W3s[d * DIM + 8 * cx + 4]);
        const unsigned long long ga = dup2(g.x), gb = dup2(g.y),
                                 gc = dup2(g.z), gd = dup2(g.w);
        fma2(acc[0][0], ga, w0.x); fma2(acc[0][1], ga, w0.y);
        fma2(acc[0][2], ga, w1.x); fma2(acc[0][3], ga, w1.y);
        fma2(acc[1][0], gb, w0.x); fma2(acc[1][1], gb, w0.y);
        fma2(acc[1][2], gb, w1.x); fma2(acc[1][3], gb, w1.y);
        fma2(acc[2][0], gc, w0.x); fma2(acc[2][1], gc, w0.y);
        fma2(acc[2][2], gc, w1.x); fma2(acc[2][3], gc, w1.y);
        fma2(acc[3][0], gd, w0.x); fma2(acc[3][1], gd, w0.y);
        fma2(acc[3][2], gd, w1.x); fma2(acc[3][3], gd, w1.y);
    }

    const float4 bA = *reinterpret_cast<const float4*>(&b3[8 * cx]);
    const float4 bB = *reinterpret_cast<const float4*>(&b3[8 * cx + 4]);
#pragma unroll
    for (int i = 0; i < 4; i++) {
        const int row = nbase + 4 * py + i;
        const float* fp = feats + (size_t)row * DIM + 8 * cx;
        const float4 f0 = *reinterpret_cast<const float4*>(fp);
        const float4 f1 = *reinterpret_cast<const float4*>(fp + 4);
        const float2 a0 = upk(acc[i][0]), a1 = upk(acc[i][1]);
        const float2 a2 = upk(acc[i][2]), a3 = upk(acc[i][3]);
        float4 r0, r1;
        r0.x = fmaxf(f0.x - fmaxf(a0.x + bA.x, 0.f), 0.f);
        r0.y = fmaxf(f0.y - fmaxf(a0.y + bA.y, 0.f), 0.f);
        r0.z = fmaxf(f0.z - fmaxf(a1.x + bA.z, 0.f), 0.f);
        r0.w = fmaxf(f0.w - fmaxf(a1.y + bA.w, 0.f), 0.f);
        r1.x = fmaxf(f1.x - fmaxf(a2.x + bB.x, 0.f), 0.f);
        r1.y = fmaxf(f1.y - fmaxf(a2.y + bB.y, 0.f), 0.f);
        r1.z = fmaxf(f1.z - fmaxf(a3.x + bB.z, 0.f), 0.f);
        r1.w = fmaxf(f1.w - fmaxf(a3.y + bB.w, 0.f), 0.f);
        float* op = out + (size_t)row * DIM + 8 * cx;
        *reinterpret_cast<float4*>(op)     = r0;
        *reinterpret_cast<float4*>(op + 4) = r1;
    }
}

// ---------------- launch ----------------
extern "C" void kernel_launch(void* const* d_in, const int* in_sizes, int n_in,
                              void* d_out, int out_size) {
    const float* feats = (const float*)d_in[0];
    const int* nidx = (const int*)d_in[1];
    const int* nmask = (const int*)d_in[2];   // bool materialized as int32
    const int* segid = (const int*)d_in[3];
    const int o = (n_in >= 11) ? 1 : 0;
    const float* W1 = (const float*)d_in[4 + o];
    const float* b1 = (const float*)d_in[5 + o];
    const float* W2 = (const float*)d_in[6 + o];
    const float* b2 = (const float*)d_in[7 + o];
    const float* W3 = (const float*)d_in[8 + o];
    const float* b3 = (const float*)d_in[9 + o];
    float* out = (float*)d_out;

    const size_t smem_fin = (size_t)(DIM * DIM + DIM * FTILE + NTHR + FTILE) * 4;

    cudaFuncSetAttribute(conv_mma_kernel, cudaFuncAttributeMaxDynamicSharedMemorySize,
                         SM_TOTAL);
    cudaFuncSetAttribute(finalize_kernel, cudaFuncAttributeMaxDynamicSharedMemorySize,
                         (int)smem_fin);

    split_feats_kernel<<<(N_PTS * DIM) / (NTHR * 4), NTHR>>>(feats);
    prep_w_kernel<<<(KNB * 2 * DIM * DIM) / NTHR, NTHR>>>(W1, W2);
    zero_seg_kernel<<<1, 1024>>>();

    conv_mma_kernel<<<NBLK, CTHR, SM_TOTAL>>>(nidx, nmask, b1, b2);

    segreduce_kernel<<<(N_PTS + 511) / 512, 256>>>(segid);
    segmean_kernel<<<1, 1024>>>();

    finalize_kernel<<<N_PTS / FTILE, NTHR, smem_fin>>>(feats, segid, W3, b3, out);
}